// round 1
// baseline (speedup 1.0000x reference)
#include <cuda_runtime.h>

#define NN 100000
#define EE 1600000
#define D  128

// ---------------- device scratch (no allocations allowed) ----------------
__device__ int   g_deg[NN];
__device__ int   g_rowptr[NN + 1];
__device__ int   g_cursor[NN];
__device__ int   g_col[EE];
__device__ int   g_bsum[512];
__device__ float g_mean[(size_t)NN * D];
__device__ float g_h[(size_t)NN * D];

// ---------------- CSR build ----------------
__global__ void zero_deg_kernel() {
    int i = blockIdx.x * blockDim.x + threadIdx.x;
    if (i < NN) g_deg[i] = 0;
}

__global__ void hist_kernel(const int* __restrict__ dst) {
    int e = blockIdx.x * blockDim.x + threadIdx.x;
    if (e < EE) atomicAdd(&g_deg[dst[e]], 1);
}

__global__ void scan_local_kernel() {
    __shared__ int s[256];
    int t = threadIdx.x;
    int i = blockIdx.x * 256 + t;
    int v = (i < NN) ? g_deg[i] : 0;
    s[t] = v;
    __syncthreads();
    for (int off = 1; off < 256; off <<= 1) {
        int add = (t >= off) ? s[t - off] : 0;
        __syncthreads();
        s[t] += add;
        __syncthreads();
    }
    if (i < NN) g_rowptr[i] = s[t] - v;       // local exclusive
    if (t == 255) g_bsum[blockIdx.x] = s[255]; // block total
}

__global__ void scan_bsum_kernel(int nb) {
    __shared__ int s[512];
    int t = threadIdx.x;
    int v = (t < nb) ? g_bsum[t] : 0;
    s[t] = v;
    __syncthreads();
    for (int off = 1; off < 512; off <<= 1) {
        int add = (t >= off) ? s[t - off] : 0;
        __syncthreads();
        s[t] += add;
        __syncthreads();
    }
    if (t < nb) g_bsum[t] = s[t] - v;          // exclusive
}

__global__ void add_off_kernel() {
    int i = blockIdx.x * blockDim.x + threadIdx.x;
    if (i < NN) {
        int r = g_rowptr[i] + g_bsum[i >> 8];
        g_rowptr[i] = r;
        g_cursor[i] = r;
    }
    if (i == 0) g_rowptr[NN] = EE;
}

__global__ void fill_kernel(const int* __restrict__ src, const int* __restrict__ dst) {
    int e = blockIdx.x * blockDim.x + threadIdx.x;
    if (e < EE) {
        int d = dst[e];
        int p = atomicAdd(&g_cursor[d], 1);
        g_col[p] = src[e];
    }
}

// ---------------- aggregation: warp per dst node, gather via CSR ----------------
__global__ void agg_kernel(const float* __restrict__ x, float* __restrict__ mean) {
    int gt   = blockIdx.x * blockDim.x + threadIdx.x;
    int w    = gt >> 5;
    int lane = gt & 31;
    if (w >= NN) return;
    int beg = g_rowptr[w], end = g_rowptr[w + 1];
    const float4* x4 = (const float4*)x;
    float4 acc = make_float4(0.f, 0.f, 0.f, 0.f);
    for (int e = beg; e < end; e++) {
        int s = g_col[e];
        float4 v = x4[(size_t)s * 32 + lane];
        acc.x += v.x; acc.y += v.y; acc.z += v.z; acc.w += v.w;
    }
    int dcount = end - beg;
    float inv = (dcount > 0) ? 1.0f / (float)dcount : 0.0f;
    acc.x *= inv; acc.y *= inv; acc.z *= inv; acc.w *= inv;
    ((float4*)mean)[(size_t)w * 32 + lane] = acc;
}

// ---------------- fused GEMM: out = X@Wself + M@Wneigh + b (+ReLU) ----------------
// 256 threads, 128 rows/block, 8x8 register tile per thread.
// W matrices resident in smem in natural [k][j] layout (conflict-free:
// 16 consecutive lanes read 16 consecutive j). X/M staged in 32-wide k chunks.
#define SM_W   (D * D)            // 16384 floats per matrix
#define SM_TP  36                 // x/mean tile row pitch (floats), 16B aligned
#define SMEM_FLOATS (2 * SM_W + 2 * 128 * SM_TP)

template <bool RELU>
__global__ void __launch_bounds__(256, 1)
gemm_kernel(const float* __restrict__ X, const float* __restrict__ M,
            const float* __restrict__ Wself, const float* __restrict__ Wneigh,
            const float* __restrict__ bias, float* __restrict__ out) {
    extern __shared__ float sm[];
    float* Ws = sm;
    float* Wn = Ws + SM_W;
    float* Xs = Wn + SM_W;            // [128][SM_TP]
    float* Ms = Xs + 128 * SM_TP;

    const int tid = threadIdx.x;
    for (int idx = tid; idx < SM_W; idx += 256) {
        Ws[idx] = Wself[idx];
        Wn[idx] = Wneigh[idx];
    }

    const int colId  = tid & 15;    // 16 column-threads, 8 cols each (stride 16)
    const int rowGrp = tid >> 4;    // 16 row groups, 8 rows each
    const int rBase  = rowGrp * 8;
    const int row0   = blockIdx.x * 128;

    float acc[8][8];
#pragma unroll
    for (int r = 0; r < 8; r++)
#pragma unroll
        for (int c = 0; c < 8; c++) acc[r][c] = 0.f;

    for (int k0 = 0; k0 < D; k0 += 32) {
        __syncthreads();
        // stage X/M chunk: 128 rows x 32 k-values, float4 vectorized
        for (int idx = tid; idx < 128 * 8; idx += 256) {
            int r  = idx >> 3;
            int kk = (idx & 7) << 2;
            int gr = row0 + r;
            float4 xv, mv;
            if (gr < NN) {
                xv = *(const float4*)(X + (size_t)gr * D + k0 + kk);
                mv = *(const float4*)(M + (size_t)gr * D + k0 + kk);
            } else {
                xv = make_float4(0.f, 0.f, 0.f, 0.f);
                mv = xv;
            }
            *(float4*)(Xs + r * SM_TP + kk) = xv;
            *(float4*)(Ms + r * SM_TP + kk) = mv;
        }
        __syncthreads();

#pragma unroll
        for (int kk = 0; kk < 32; kk += 4) {
            float4 xr[8], mr[8];
#pragma unroll
            for (int r = 0; r < 8; r++) {
                xr[r] = *(float4*)(Xs + (rBase + r) * SM_TP + kk);
                mr[r] = *(float4*)(Ms + (rBase + r) * SM_TP + kk);
            }
#pragma unroll
            for (int c = 0; c < 8; c++) {
                int j = colId + 16 * c;
                const float* wsp = Ws + (k0 + kk) * D + j;
                const float* wnp = Wn + (k0 + kk) * D + j;
#pragma unroll
                for (int q = 0; q < 4; q++) {
                    float ws = wsp[q * D];
                    float wn = wnp[q * D];
#pragma unroll
                    for (int r = 0; r < 8; r++) {
                        float xv = (q == 0) ? xr[r].x : (q == 1) ? xr[r].y : (q == 2) ? xr[r].z : xr[r].w;
                        float mv = (q == 0) ? mr[r].x : (q == 1) ? mr[r].y : (q == 2) ? mr[r].z : mr[r].w;
                        acc[r][c] = fmaf(xv, ws, acc[r][c]);
                        acc[r][c] = fmaf(mv, wn, acc[r][c]);
                    }
                }
            }
        }
    }

    // epilogue: bias (+ReLU), store
#pragma unroll
    for (int c = 0; c < 8; c++) {
        int j = colId + 16 * c;
        float b = bias[j];
#pragma unroll
        for (int r = 0; r < 8; r++) {
            int gr = row0 + rBase + r;
            if (gr < NN) {
                float v = acc[r][c] + b;
                if (RELU) v = fmaxf(v, 0.f);
                out[(size_t)gr * D + j] = v;
            }
        }
    }
}

// ---------------- launch ----------------
extern "C" void kernel_launch(void* const* d_in, const int* in_sizes, int n_in,
                              void* d_out, int out_size) {
    const float* x   = (const float*)d_in[0];
    const float* W1s = (const float*)d_in[1];
    const float* W1n = (const float*)d_in[2];
    const float* b1  = (const float*)d_in[3];
    const float* W2s = (const float*)d_in[4];
    const float* W2n = (const float*)d_in[5];
    const float* b2  = (const float*)d_in[6];
    const int*   src = (const int*)d_in[7];
    const int*   dst = (const int*)d_in[8];
    float* out = (float*)d_out;

    float *mean, *h;
    cudaGetSymbolAddress((void**)&mean, g_mean);
    cudaGetSymbolAddress((void**)&h, g_h);

    const size_t SMEM = SMEM_FLOATS * sizeof(float); // ~164 KB
    cudaFuncSetAttribute(gemm_kernel<true>,  cudaFuncAttributeMaxDynamicSharedMemorySize, (int)SMEM);
    cudaFuncSetAttribute(gemm_kernel<false>, cudaFuncAttributeMaxDynamicSharedMemorySize, (int)SMEM);

    const int nbScan = (NN + 255) / 256; // 391

    // CSR build (per call — deterministic work)
    zero_deg_kernel<<<(NN + 255) / 256, 256>>>();
    hist_kernel<<<(EE + 255) / 256, 256>>>(dst);
    scan_local_kernel<<<nbScan, 256>>>();
    scan_bsum_kernel<<<1, 512>>>(nbScan);
    add_off_kernel<<<(NN + 255) / 256, 256>>>();
    fill_kernel<<<(EE + 255) / 256, 256>>>(src, dst);

    // layer 1
    agg_kernel<<<(NN * 32 + 255) / 256, 256>>>(x, mean);
    gemm_kernel<true><<<(NN + 127) / 128, 256, SMEM>>>(x, mean, W1s, W1n, b1, h);

    // layer 2
    agg_kernel<<<(NN * 32 + 255) / 256, 256>>>(h, mean);
    gemm_kernel<false><<<(NN + 127) / 128, 256, SMEM>>>(h, mean, W2s, W2n, b2, out);
}

// round 4
// speedup vs baseline: 2.0879x; 2.0879x over previous
#include <cuda_runtime.h>
#include <cuda_bf16.h>
#include <cstdint>

#define NN 100000
#define EE 1600000
#define D  128

// ---------------- device scratch (no allocations allowed) ----------------
__device__ int   g_deg[NN];
__device__ int   g_rowptr[NN + 1];
__device__ int   g_cursor[NN];
__device__ int   g_col[EE];
__device__ int   g_bsum[512];
__device__ float g_mean[(size_t)NN * D];
__device__ float g_h[(size_t)NN * D];
// W transposed+split: [j=0..127][k=0..255] bf16, k<128 -> Wself[k][j], k>=128 -> Wneigh[k-128][j]
__device__ __nv_bfloat16 g_WT1h[128 * 256];
__device__ __nv_bfloat16 g_WT1l[128 * 256];
__device__ __nv_bfloat16 g_WT2h[128 * 256];
__device__ __nv_bfloat16 g_WT2l[128 * 256];

// ---------------- CSR build ----------------
__global__ void zero_deg_kernel() {
    int i = blockIdx.x * blockDim.x + threadIdx.x;
    if (i < NN) g_deg[i] = 0;
}
__global__ void hist_kernel(const int* __restrict__ dst) {
    int e = blockIdx.x * blockDim.x + threadIdx.x;
    if (e < EE) atomicAdd(&g_deg[dst[e]], 1);
}
__global__ void scan_local_kernel() {
    __shared__ int s[256];
    int t = threadIdx.x;
    int i = blockIdx.x * 256 + t;
    int v = (i < NN) ? g_deg[i] : 0;
    s[t] = v;
    __syncthreads();
    for (int off = 1; off < 256; off <<= 1) {
        int add = (t >= off) ? s[t - off] : 0;
        __syncthreads();
        s[t] += add;
        __syncthreads();
    }
    if (i < NN) g_rowptr[i] = s[t] - v;
    if (t == 255) g_bsum[blockIdx.x] = s[255];
}
__global__ void scan_bsum_kernel(int nb) {
    __shared__ int s[512];
    int t = threadIdx.x;
    int v = (t < nb) ? g_bsum[t] : 0;
    s[t] = v;
    __syncthreads();
    for (int off = 1; off < 512; off <<= 1) {
        int add = (t >= off) ? s[t - off] : 0;
        __syncthreads();
        s[t] += add;
        __syncthreads();
    }
    if (t < nb) g_bsum[t] = s[t] - v;
}
__global__ void add_off_kernel() {
    int i = blockIdx.x * blockDim.x + threadIdx.x;
    if (i < NN) {
        int r = g_rowptr[i] + g_bsum[i >> 8];
        g_rowptr[i] = r;
        g_cursor[i] = r;
    }
    if (i == 0) g_rowptr[NN] = EE;
}
__global__ void fill_kernel(const int* __restrict__ src, const int* __restrict__ dst) {
    int e = blockIdx.x * blockDim.x + threadIdx.x;
    if (e < EE) {
        int d = dst[e];
        int p = atomicAdd(&g_cursor[d], 1);
        g_col[p] = src[e];
    }
}

// ---------------- aggregation: warp per dst node, gather via CSR ----------------
__global__ void agg_kernel(const float* __restrict__ x, float* __restrict__ mean) {
    int gt   = blockIdx.x * blockDim.x + threadIdx.x;
    int w    = gt >> 5;
    int lane = gt & 31;
    if (w >= NN) return;
    int beg = g_rowptr[w], end = g_rowptr[w + 1];
    const float4* x4 = (const float4*)x;
    float4 acc = make_float4(0.f, 0.f, 0.f, 0.f);
    for (int e = beg; e < end; e++) {
        int s = g_col[e];
        float4 v = x4[(size_t)s * 32 + lane];
        acc.x += v.x; acc.y += v.y; acc.z += v.z; acc.w += v.w;
    }
    int dcount = end - beg;
    float inv = (dcount > 0) ? 1.0f / (float)dcount : 0.0f;
    acc.x *= inv; acc.y *= inv; acc.z *= inv; acc.w *= inv;
    ((float4*)mean)[(size_t)w * 32 + lane] = acc;
}

// ---------------- weight prep: WT[j][k] = concat(Ws,Wn)[k][j], split hi/lo bf16 ----------------
__global__ void prep_wt_kernel(const float* __restrict__ W1s, const float* __restrict__ W1n,
                               const float* __restrict__ W2s, const float* __restrict__ W2n) {
    int idx = blockIdx.x * blockDim.x + threadIdx.x;   // 2 * 32768 total
    if (idx >= 2 * 128 * 256) return;
    int layer = idx >> 15;
    int e = idx & 32767;
    int j = e >> 8;          // 0..127 output column
    int k = e & 255;         // 0..255 concat K
    const float* Ws = layer ? W2s : W1s;
    const float* Wn = layer ? W2n : W1n;
    float v = (k < 128) ? Ws[k * 128 + j] : Wn[(k - 128) * 128 + j];
    __nv_bfloat16 hi = __float2bfloat16(v);
    __nv_bfloat16 lo = __float2bfloat16(v - __bfloat162float(hi));
    if (layer) { g_WT2h[e] = hi; g_WT2l[e] = lo; }
    else       { g_WT1h[e] = hi; g_WT1l[e] = lo; }
}

// ---------------- HMMA GEMM: out = X@Ws + M@Wn + b (+ReLU), split-bf16 3-term ----------------
// mma.sync.m16n8k16 row.col f32.bf16.bf16.f32 (compiles at compute_103, runs on tensor pipe).
// CTA 128x128, 8 warps (4m x 2n), warp tile 32x64, K=256 in 4 chunks of 64.
#define APITCH 72   // bf16 units per smem row (144 B) -> conflict-free frag loads
#define SM_BF16 (4 * 128 * APITCH)              // Ah, Al, Bh, Bl
#define SM_BYTES (SM_BF16 * 2)                  // 73728

__device__ __forceinline__ void mma_bf16(float* c, const uint32_t* a, uint32_t b0, uint32_t b1) {
    asm volatile("mma.sync.aligned.m16n8k16.row.col.f32.bf16.bf16.f32 "
                 "{%0,%1,%2,%3}, {%4,%5,%6,%7}, {%8,%9}, {%0,%1,%2,%3};"
                 : "+f"(c[0]), "+f"(c[1]), "+f"(c[2]), "+f"(c[3])
                 : "r"(a[0]), "r"(a[1]), "r"(a[2]), "r"(a[3]), "r"(b0), "r"(b1));
}

template <bool RELU>
__global__ void __launch_bounds__(256, 2)
gemm_hmma_kernel(const float* __restrict__ X, const float* __restrict__ Mn,
                 const __nv_bfloat16* __restrict__ WTh, const __nv_bfloat16* __restrict__ WTl,
                 const float* __restrict__ bias, float* __restrict__ out) {
    extern __shared__ __nv_bfloat16 sm[];
    __nv_bfloat16* Ah = sm;
    __nv_bfloat16* Al = Ah + 128 * APITCH;
    __nv_bfloat16* Bh = Al + 128 * APITCH;
    __nv_bfloat16* Bl = Bh + 128 * APITCH;

    const int tid  = threadIdx.x;
    const int wid  = tid >> 5;
    const int lane = tid & 31;
    const int grp  = lane >> 2;   // 0..7
    const int qp   = lane & 3;    // 0..3
    const int wm   = wid >> 1;    // 0..3 -> rows wm*32
    const int wn   = wid & 1;     // 0..1 -> cols wn*64
    const int row0 = blockIdx.x * 128;

    float acc[2][8][4];
#pragma unroll
    for (int mf = 0; mf < 2; mf++)
#pragma unroll
        for (int nf = 0; nf < 8; nf++)
#pragma unroll
            for (int q = 0; q < 4; q++) acc[mf][nf][q] = 0.f;

#pragma unroll
    for (int chunk = 0; chunk < 4; chunk++) {
        const float* A = (chunk < 2) ? X : Mn;
        const int kc = (chunk & 1) * 64;   // source col base within the 128-wide matrix
        const int k0 = chunk * 64;         // concat-K base (for B)

        __syncthreads();  // previous chunk's compute done before smem overwrite

        // stage A: 128 rows x 64 cols fp32 -> hi/lo bf16 (2048 float4, 8/thread)
#pragma unroll
        for (int i = 0; i < 8; i++) {
            int idx = tid + i * 256;
            int r   = idx >> 4;
            int kq  = (idx & 15) << 2;
            int gr  = row0 + r;
            float4 v = (gr < NN) ? *(const float4*)(A + (size_t)gr * D + kc + kq)
                                 : make_float4(0.f, 0.f, 0.f, 0.f);
            __nv_bfloat16 h0 = __float2bfloat16(v.x), h1 = __float2bfloat16(v.y);
            __nv_bfloat16 h2 = __float2bfloat16(v.z), h3 = __float2bfloat16(v.w);
            __nv_bfloat16 l0 = __float2bfloat16(v.x - __bfloat162float(h0));
            __nv_bfloat16 l1 = __float2bfloat16(v.y - __bfloat162float(h1));
            __nv_bfloat16 l2 = __float2bfloat16(v.z - __bfloat162float(h2));
            __nv_bfloat16 l3 = __float2bfloat16(v.w - __bfloat162float(h3));
            uint2 hw, lw;
            hw.x = (uint32_t)__bfloat16_as_ushort(h0) | ((uint32_t)__bfloat16_as_ushort(h1) << 16);
            hw.y = (uint32_t)__bfloat16_as_ushort(h2) | ((uint32_t)__bfloat16_as_ushort(h3) << 16);
            lw.x = (uint32_t)__bfloat16_as_ushort(l0) | ((uint32_t)__bfloat16_as_ushort(l1) << 16);
            lw.y = (uint32_t)__bfloat16_as_ushort(l2) | ((uint32_t)__bfloat16_as_ushort(l3) << 16);
            *(uint2*)(Ah + r * APITCH + kq) = hw;
            *(uint2*)(Al + r * APITCH + kq) = lw;
        }

        // stage B: WT[j][k0..k0+63] hi+lo (2048 uint4 total, 8/thread)
#pragma unroll
        for (int i = 0; i < 8; i++) {
            int idx = tid + i * 256;
            int mat = idx >> 10;           // 0 = hi, 1 = lo
            int e   = idx & 1023;
            int r   = e >> 3;              // j
            int kq  = (e & 7) << 3;        // 8 bf16 per uint4
            const uint4* src = (const uint4*)(mat ? WTl : WTh);
            uint4 v = src[r * 32 + ((k0 + kq) >> 3)];
            *(uint4*)((mat ? Bl : Bh) + r * APITCH + kq) = v;
        }
        __syncthreads();

        // compute: 4 k-steps of 16
#pragma unroll
        for (int ks = 0; ks < 64; ks += 16) {
            uint32_t ah[2][4], al[2][4];
#pragma unroll
            for (int mf = 0; mf < 2; mf++) {
                int rb = wm * 32 + mf * 16;
                const __nv_bfloat16* pAh = Ah + (rb + grp) * APITCH + ks + qp * 2;
                const __nv_bfloat16* pAl = Al + (rb + grp) * APITCH + ks + qp * 2;
                ah[mf][0] = *(const uint32_t*)(pAh);
                ah[mf][1] = *(const uint32_t*)(pAh + 8 * APITCH);
                ah[mf][2] = *(const uint32_t*)(pAh + 8);
                ah[mf][3] = *(const uint32_t*)(pAh + 8 * APITCH + 8);
                al[mf][0] = *(const uint32_t*)(pAl);
                al[mf][1] = *(const uint32_t*)(pAl + 8 * APITCH);
                al[mf][2] = *(const uint32_t*)(pAl + 8);
                al[mf][3] = *(const uint32_t*)(pAl + 8 * APITCH + 8);
            }
#pragma unroll
            for (int nf = 0; nf < 8; nf++) {
                int j = wn * 64 + nf * 8 + grp;
                const __nv_bfloat16* pBh = Bh + j * APITCH + ks + qp * 2;
                const __nv_bfloat16* pBl = Bl + j * APITCH + ks + qp * 2;
                uint32_t bh0 = *(const uint32_t*)(pBh);
                uint32_t bh1 = *(const uint32_t*)(pBh + 8);
                uint32_t bl0 = *(const uint32_t*)(pBl);
                uint32_t bl1 = *(const uint32_t*)(pBl + 8);
                mma_bf16(acc[0][nf], ah[0], bh0, bh1);   // Ah*Bh
                mma_bf16(acc[1][nf], ah[1], bh0, bh1);
                mma_bf16(acc[0][nf], al[0], bh0, bh1);   // Al*Bh
                mma_bf16(acc[1][nf], al[1], bh0, bh1);
                mma_bf16(acc[0][nf], ah[0], bl0, bl1);   // Ah*Bl
                mma_bf16(acc[1][nf], ah[1], bl0, bl1);
            }
        }
    }

    // epilogue: bias (+ReLU), float2 stores
#pragma unroll
    for (int mf = 0; mf < 2; mf++) {
#pragma unroll
        for (int nf = 0; nf < 8; nf++) {
            int c = wn * 64 + nf * 8 + qp * 2;
            int r = row0 + wm * 32 + mf * 16 + grp;
            float bx = bias[c], by = bias[c + 1];
            float2 v0, v1;
            v0.x = acc[mf][nf][0] + bx; v0.y = acc[mf][nf][1] + by;
            v1.x = acc[mf][nf][2] + bx; v1.y = acc[mf][nf][3] + by;
            if (RELU) {
                v0.x = fmaxf(v0.x, 0.f); v0.y = fmaxf(v0.y, 0.f);
                v1.x = fmaxf(v1.x, 0.f); v1.y = fmaxf(v1.y, 0.f);
            }
            if (r < NN)     *(float2*)(out + (size_t)r * D + c) = v0;
            if (r + 8 < NN) *(float2*)(out + (size_t)(r + 8) * D + c) = v1;
        }
    }
}

// ---------------- launch ----------------
extern "C" void kernel_launch(void* const* d_in, const int* in_sizes, int n_in,
                              void* d_out, int out_size) {
    const float* x   = (const float*)d_in[0];
    const float* W1s = (const float*)d_in[1];
    const float* W1n = (const float*)d_in[2];
    const float* b1  = (const float*)d_in[3];
    const float* W2s = (const float*)d_in[4];
    const float* W2n = (const float*)d_in[5];
    const float* b2  = (const float*)d_in[6];
    const int*   src = (const int*)d_in[7];
    const int*   dst = (const int*)d_in[8];
    float* out = (float*)d_out;

    float *mean, *h;
    __nv_bfloat16 *wt1h, *wt1l, *wt2h, *wt2l;
    cudaGetSymbolAddress((void**)&mean, g_mean);
    cudaGetSymbolAddress((void**)&h, g_h);
    cudaGetSymbolAddress((void**)&wt1h, g_WT1h);
    cudaGetSymbolAddress((void**)&wt1l, g_WT1l);
    cudaGetSymbolAddress((void**)&wt2h, g_WT2h);
    cudaGetSymbolAddress((void**)&wt2l, g_WT2l);

    cudaFuncSetAttribute(gemm_hmma_kernel<true>,  cudaFuncAttributeMaxDynamicSharedMemorySize, SM_BYTES);
    cudaFuncSetAttribute(gemm_hmma_kernel<false>, cudaFuncAttributeMaxDynamicSharedMemorySize, SM_BYTES);

    const int nbScan   = (NN + 255) / 256;   // 391
    const int gemmGrid = (NN + 127) / 128;   // 782

    // CSR build
    zero_deg_kernel<<<(NN + 255) / 256, 256>>>();
    hist_kernel<<<(EE + 255) / 256, 256>>>(dst);
    scan_local_kernel<<<nbScan, 256>>>();
    scan_bsum_kernel<<<1, 512>>>(nbScan);
    add_off_kernel<<<(NN + 255) / 256, 256>>>();
    fill_kernel<<<(EE + 255) / 256, 256>>>(src, dst);

    // weight prep
    prep_wt_kernel<<<(2 * 128 * 256 + 255) / 256, 256>>>(W1s, W1n, W2s, W2n);

    // layer 1
    agg_kernel<<<(NN * 32 + 255) / 256, 256>>>(x, mean);
    gemm_hmma_kernel<true><<<gemmGrid, 256, SM_BYTES>>>(x, mean, wt1h, wt1l, b1, h);

    // layer 2
    agg_kernel<<<(NN * 32 + 255) / 256, 256>>>(h, mean);
    gemm_hmma_kernel<false><<<gemmGrid, 256, SM_BYTES>>>(h, mean, wt2h, wt2l, b2, out);
}